// round 3
// baseline (speedup 1.0000x reference)
#include <cuda_runtime.h>
#include <cuda_bf16.h>
#include <cstdint>

#define BB 2
#define CC 16
#define NN 6912          // 72*96
#define BT 128           // threads per block (4 warps)
#define MW 32            // i rows per warp
#define IT 128           // i rows per block
#define JCH 128          // j chunk in smem
#define JPAD 136         // padded j stride for bf16 tiles
#define JSPLIT 18
#define JBLK (NN / JSPLIT)                 // 384 j per block
#define NBLK (JSPLIT * (NN / IT) * BB)     // 1944 pair blocks

#define S1 14.426950408889634f   // 10*log2(e)
#define S2 28.853900817779268f   // 20*log2(e)

// ---------------- scratch ----------------
__device__ float4 g_p1s[BB * NN];            // (2S x1, 2S y1, 2S z1, e_c1)
__device__ float4 g_p2t[BB * NN];            // (xt, yt, zt, -S|pt|^2)
__device__ float4 g_p2n[BB * NN];            // (x2, y2, z2, -S|p2|^2)
__device__ float  g_f1e[BB * NN * CC];       // f1n * mask * e_c1, [b][i][c]
__device__ unsigned short g_f2h[BB * CC * NN];  // bf16 hi of f2n, [b][c][j]
__device__ unsigned short g_f2l[BB * CC * NN];  // bf16 lo
__device__ double g_acc[BB];
__device__ double g_sm1[BB], g_sm2[BB];
__device__ double g_fns;
__device__ unsigned int g_cnt;               // block completion counter (self-resetting)

// ---------------- helpers ----------------
__device__ __forceinline__ float ex2f(float x) {
    float r; asm("ex2.approx.ftz.f32 %0, %1;" : "=f"(r) : "f"(x)); return r;
}
__device__ __forceinline__ unsigned short bf16_bits(float v) {
    unsigned short u; asm("cvt.rn.bf16.f32 %0, %1;" : "=h"(u) : "f"(v)); return u;
}
__device__ __forceinline__ float bf16_val(unsigned short u) {
    return __uint_as_float(((uint32_t)u) << 16);
}
__device__ __forceinline__ uint32_t pack_bf2(float lo, float hi) {
    uint32_t r; asm("cvt.rn.bf16x2.f32 %0, %1, %2;" : "=r"(r) : "f"(hi), "f"(lo)); return r;
}
__device__ __forceinline__ void split2(float d0, float d1, uint32_t& h, uint32_t& l) {
    h = pack_bf2(d0, d1);
    float h0 = __uint_as_float(h << 16);
    float h1 = __uint_as_float(h & 0xFFFF0000u);
    l = pack_bf2(d0 - h0, d1 - h1);
}
// packed f32x2 ops (sm_100+)
__device__ __forceinline__ uint64_t pk2(float v) {
    uint64_t r; asm("mov.b64 %0, {%1, %2};" : "=l"(r) : "f"(v), "f"(v)); return r;
}
__device__ __forceinline__ uint64_t fma2(uint64_t a, uint64_t b, uint64_t c) {
    uint64_t r; asm("fma.rn.f32x2 %0, %1, %2, %3;" : "=l"(r) : "l"(a), "l"(b), "l"(c)); return r;
}
__device__ __forceinline__ void upk(uint64_t v, float& lo, float& hi) {
    asm("mov.b64 {%0, %1}, %2;" : "=f"(lo), "=f"(hi) : "l"(v));
}
// D pair = ex2(argT) - ex2(argN) for packed (j0,j1) args
__device__ __forceinline__ void argd(uint64_t at, uint64_t an, float& d0, float& d1) {
    float tl, th, nl, nh;
    upk(at, tl, th); upk(an, nl, nh);
    d0 = ex2f(tl) - ex2f(nl);
    d1 = ex2f(th) - ex2f(nh);
}
__device__ __forceinline__ void mma_bf16(float* c, const uint32_t* a, const uint32_t* b) {
    asm volatile(
        "mma.sync.aligned.m16n8k16.row.col.f32.bf16.bf16.f32 "
        "{%0,%1,%2,%3}, {%4,%5,%6,%7}, {%8,%9}, {%0,%1,%2,%3};"
        : "+f"(c[0]), "+f"(c[1]), "+f"(c[2]), "+f"(c[3])
        : "r"(a[0]), "r"(a[1]), "r"(a[2]), "r"(a[3]), "r"(b[0]), "r"(b[1]));
}

// ---------------- kernels ----------------
__global__ void prep_kernel(const float* __restrict__ f1,
                            const float* __restrict__ f2,
                            const float* __restrict__ d1,
                            const float* __restrict__ d2,
                            const float* __restrict__ pose,
                            const float* __restrict__ yz1) {
    int gid = blockIdx.x * blockDim.x + threadIdx.x;   // BB*NN threads
    int b = gid / NN, i = gid % NN;

    float dd1 = d1[gid], dd2 = d2[gid];
    float m1 = dd1 > 0.f ? 1.f : 0.f;
    float m2 = dd2 > 0.f ? 1.f : 0.f;

    float gx = yz1[i], gy = yz1[NN + i], gz = yz1[2 * NN + i];
    float x1 = gx * dd1, y1 = gy * dd1, z1 = gz * dd1;
    float x2 = gx * dd2, y2 = gy * dd2, z2 = gz * dd2;

    const float* Pm = pose + b * 16;
    float xt = Pm[0]*x2 + Pm[1]*y2 + Pm[2] *z2 + Pm[3];
    float yt = Pm[4]*x2 + Pm[5]*y2 + Pm[6] *z2 + Pm[7];
    float zt = Pm[8]*x2 + Pm[9]*y2 + Pm[10]*z2 + Pm[11];

    float q1 = x1*x1 + y1*y1 + z1*z1;
    float e1 = ex2f(-S1 * q1);                       // 2^{c1}
    g_p1s[gid] = make_float4(S2*x1, S2*y1, S2*z1, e1);
    g_p2t[gid] = make_float4(xt, yt, zt, -S1*(xt*xt + yt*yt + zt*zt));
    g_p2n[gid] = make_float4(x2, y2, z2, -S1*(x2*x2 + y2*y2 + z2*z2));

    float a1[CC], a2[CC];
    float s1 = 0.f, s2 = 0.f;
#pragma unroll
    for (int c = 0; c < CC; c++) {
        float v = f1[(b * CC + c) * NN + i]; a1[c] = v; s1 += v * v;
        float w = f2[(b * CC + c) * NN + i]; a2[c] = w; s2 += w * w;
    }
    float n1 = sqrtf(s1), n2 = sqrtf(s2);
    float r1 = m1 / (n1 + 1e-8f), r2 = m2 / (n2 + 1e-8f);
#pragma unroll
    for (int c = 0; c < CC; c++) {
        g_f1e[gid * CC + c] = a1[c] * r1 * e1;       // fold 2^{c1} into f1
        float w = a2[c] * r2;
        unsigned short hb = bf16_bits(w);
        float hv = bf16_val(hb);
        g_f2h[(b * CC + c) * NN + i] = hb;
        g_f2l[(b * CC + c) * NN + i] = bf16_bits(w - hv);
    }

    float vm1 = m1, vm2 = m2, vf = 100.f * (n1 * m1 + n2 * m2);
#pragma unroll
    for (int o = 16; o > 0; o >>= 1) {
        vm1 += __shfl_down_sync(0xffffffffu, vm1, o);
        vm2 += __shfl_down_sync(0xffffffffu, vm2, o);
        vf  += __shfl_down_sync(0xffffffffu, vf,  o);
    }
    if ((threadIdx.x & 31) == 0) {
        atomicAdd(&g_sm1[b], (double)vm1);
        atomicAdd(&g_sm2[b], (double)vm2);
        atomicAdd(&g_fns,    (double)vf);
    }
}

__global__ __launch_bounds__(BT) void pair_kernel(float* __restrict__ out, int out_size) {
    const int b    = blockIdx.z;
    const int base = b * NN;
    const int ibase = blockIdx.y * IT;
    const int warp = threadIdx.x >> 5, lane = threadIdx.x & 31;
    const int r = lane >> 2, cq = lane & 3;

    // p2 tiles, j-pair interleaved: s_t[m] = {x0,x1,y0,y1,z0,z1,w0,w1} for j=2m,2m+1
    __shared__ float s_t[JCH / 2][8];
    __shared__ float s_n[JCH / 2][8];
    __shared__ unsigned short sfh[CC][JPAD], sfl[CC][JPAD];
    __shared__ float wred[BT / 32];
    __shared__ int is_last;

    // packed A broadcasts: rows 8*t + r (t = 0..3)
    uint64_t ax[4], ay[4], az[4];
#pragma unroll
    for (int t = 0; t < 4; t++) {
        float4 P = g_p1s[base + ibase + warp * MW + 8 * t + r];
        ax[t] = pk2(P.x); ay[t] = pk2(P.y); az[t] = pk2(P.z);
    }

    float acc[2][2][4];
#pragma unroll
    for (int a = 0; a < 2; a++)
#pragma unroll
        for (int n = 0; n < 2; n++)
#pragma unroll
            for (int k = 0; k < 4; k++) acc[a][n][k] = 0.f;

    for (int ch = 0; ch < JBLK / JCH; ch++) {
        const int j0 = blockIdx.x * JBLK + ch * JCH;
        __syncthreads();
        for (int idx = threadIdx.x; idx < JCH; idx += BT) {
            float4 t = g_p2t[base + j0 + idx];
            float4 n = g_p2n[base + j0 + idx];
            int m = idx >> 1, h = idx & 1;
            s_t[m][0 + h] = t.x; s_t[m][2 + h] = t.y; s_t[m][4 + h] = t.z; s_t[m][6 + h] = t.w;
            s_n[m][0 + h] = n.x; s_n[m][2 + h] = n.y; s_n[m][4 + h] = n.z; s_n[m][6 + h] = n.w;
        }
        for (int idx = threadIdx.x; idx < CC * (JCH / 2); idx += BT) {
            int c = idx >> 6, jj = idx & 63;
            ((uint32_t*)&sfh[c][0])[jj] = ((const uint32_t*)(g_f2h + (b * CC + c) * NN + j0))[jj];
            ((uint32_t*)&sfl[c][0])[jj] = ((const uint32_t*)(g_f2l + (b * CC + c) * NN + j0))[jj];
        }
        __syncthreads();

#pragma unroll 1
        for (int ks = 0; ks < JCH / 16; ks++) {
            const int kb = ks * 16 + 2 * cq;
            const int m  = ks * 8 + cq;      // j-pair index (j = kb, kb+1)
            const int mH = m + 4;            // j-pair (kb+8, kb+9)

            // packed p2 components: .x = x-pair, .y = y-pair / z-pair, w-pair
            ulonglong2 t0a = *(const ulonglong2*)&s_t[m][0];
            ulonglong2 t0b = *(const ulonglong2*)&s_t[m][4];
            ulonglong2 t8a = *(const ulonglong2*)&s_t[mH][0];
            ulonglong2 t8b = *(const ulonglong2*)&s_t[mH][4];
            ulonglong2 n0a = *(const ulonglong2*)&s_n[m][0];
            ulonglong2 n0b = *(const ulonglong2*)&s_n[m][4];
            ulonglong2 n8a = *(const ulonglong2*)&s_n[mH][0];
            ulonglong2 n8b = *(const ulonglong2*)&s_n[mH][4];

            uint32_t bh[2][2], bl[2][2];
#pragma unroll
            for (int nh = 0; nh < 2; nh++) {
                bh[nh][0] = *(const uint32_t*)&sfh[nh * 8 + r][kb];
                bh[nh][1] = *(const uint32_t*)&sfh[nh * 8 + r][kb + 8];
                bl[nh][0] = *(const uint32_t*)&sfl[nh * 8 + r][kb];
                bl[nh][1] = *(const uint32_t*)&sfl[nh * 8 + r][kb + 8];
            }
#pragma unroll
            for (int rf = 0; rf < 2; rf++) {
                uint32_t ah[4], al[4];
#pragma unroll
                for (int rr = 0; rr < 2; rr++) {
                    const int a = 2 * rf + rr;
                    uint64_t aT0 = fma2(ax[a], t0a.x, fma2(ay[a], t0a.y, fma2(az[a], t0b.x, t0b.y)));
                    uint64_t aN0 = fma2(ax[a], n0a.x, fma2(ay[a], n0a.y, fma2(az[a], n0b.x, n0b.y)));
                    uint64_t aT8 = fma2(ax[a], t8a.x, fma2(ay[a], t8a.y, fma2(az[a], t8b.x, t8b.y)));
                    uint64_t aN8 = fma2(ax[a], n8a.x, fma2(ay[a], n8a.y, fma2(az[a], n8b.x, n8b.y)));
                    float d0, d1, d8, d9;
                    argd(aT0, aN0, d0, d1);
                    argd(aT8, aN8, d8, d9);
                    split2(d0, d1, ah[rr], al[rr]);
                    split2(d8, d9, ah[2 + rr], al[2 + rr]);
                }
#pragma unroll
                for (int nh = 0; nh < 2; nh++) {
                    mma_bf16(acc[rf][nh], ah, bh[nh]);
                    mma_bf16(acc[rf][nh], ah, bl[nh]);
                    mma_bf16(acc[rf][nh], al, bh[nh]);
                }
            }
        }
    }

    // epilogue: contract C with f1e (e_c1 already folded in)
    float tot = 0.f;
#pragma unroll
    for (int rf = 0; rf < 2; rf++) {
#pragma unroll
        for (int nh = 0; nh < 2; nh++) {
            const float* F0 = g_f1e + (base + ibase + warp * MW + rf * 16 + r) * CC + nh * 8 + 2 * cq;
            const float* F1 = F0 + 8 * CC;
            tot += acc[rf][nh][0] * F0[0] + acc[rf][nh][1] * F0[1]
                 + acc[rf][nh][2] * F1[0] + acc[rf][nh][3] * F1[1];
        }
    }
#pragma unroll
    for (int o = 16; o > 0; o >>= 1) tot += __shfl_down_sync(0xffffffffu, tot, o);
    if (lane == 0) wred[warp] = tot;
    __syncthreads();
    if (threadIdx.x == 0) {
        float s = wred[0] + wred[1] + wred[2] + wred[3];
        atomicAdd(&g_acc[b], (double)s);
        __threadfence();
        unsigned int t = atomicAdd(&g_cnt, 1u);
        is_last = (t == NBLK - 1) ? 1 : 0;
    }
    __syncthreads();

    // last block: finalize + self-reset (graph-replay deterministic)
    if (is_last) {
        if (threadIdx.x == 0) {
            __threadfence();
            double total = 0.0;
            for (int bb = 0; bb < BB; bb++)
                total += -g_acc[bb] / (g_sm1[bb] * g_sm2[bb]);
            if (out_size > 0) out[0] = (float)total;
            if (out_size > 1) out[1] = (float)total;
            if (out_size > 2) out[2] = (float)g_fns;
            for (int bb = 0; bb < BB; bb++) { g_acc[bb] = 0.0; g_sm1[bb] = 0.0; g_sm2[bb] = 0.0; }
            g_fns = 0.0;
            g_cnt = 0u;
        }
        for (int idx = threadIdx.x + 3; idx < out_size; idx += BT) out[idx] = 0.f;
    }
}

extern "C" void kernel_launch(void* const* d_in, const int* in_sizes, int n_in,
                              void* d_out, int out_size) {
    const float* f1   = (const float*)d_in[0];
    const float* f2   = (const float*)d_in[1];
    const float* d1   = (const float*)d_in[2];
    const float* d2   = (const float*)d_in[3];
    const float* pose = (const float*)d_in[4];
    const float* yz1  = (const float*)d_in[7];
    float* out = (float*)d_out;

    prep_kernel<<<(BB * NN) / 256, 256>>>(f1, f2, d1, d2, pose, yz1);
    pair_kernel<<<dim3(JSPLIT, NN / IT, BB), BT>>>(out, out_size);
}

// round 4
// speedup vs baseline: 1.4543x; 1.4543x over previous
#include <cuda_runtime.h>
#include <cuda_bf16.h>
#include <cstdint>

#define BB 2
#define CC 16
#define NN 6912          // 72*96
#define BT 128           // threads per block (4 warps)
#define MW 32            // i rows per warp
#define IT 128           // i rows per block
#define JCH 128          // j chunk in smem
#define JPAD 136         // padded j stride for bf16 tiles
#define JSPLIT 18
#define JBLK (NN / JSPLIT)                 // 384 j per block
#define NBLK (JSPLIT * (NN / IT) * BB)     // 1944 pair blocks

#define S1 14.426950408889634f   // 10*log2(e)
#define S2 28.853900817779268f   // 20*log2(e)

// ---------------- scratch ----------------
__device__ float4 g_p1s[BB * NN];            // (2S x1, 2S y1, 2S z1, e_c1)
__device__ float4 g_p2t[BB * NN];            // (xt, yt, zt, -S|pt|^2)
__device__ float4 g_p2n[BB * NN];            // (x2, y2, z2, -S|p2|^2)
__device__ float  g_f1e[BB * NN * CC];       // f1n * mask * e_c1, [b][i][c]
__device__ unsigned short g_f2h[BB * CC * NN];  // bf16 hi of f2n, [b][c][j]
__device__ unsigned short g_f2l[BB * CC * NN];  // bf16 lo
__device__ double g_acc[BB];
__device__ double g_sm1[BB], g_sm2[BB];
__device__ double g_fns;
__device__ unsigned int g_cnt;               // block completion counter (self-resetting)

// ---------------- helpers ----------------
__device__ __forceinline__ float ex2f(float x) {
    float r; asm("ex2.approx.ftz.f32 %0, %1;" : "=f"(r) : "f"(x)); return r;
}
__device__ __forceinline__ unsigned short bf16_bits(float v) {
    unsigned short u; asm("cvt.rn.bf16.f32 %0, %1;" : "=h"(u) : "f"(v)); return u;
}
__device__ __forceinline__ float bf16_val(unsigned short u) {
    return __uint_as_float(((uint32_t)u) << 16);
}
__device__ __forceinline__ uint32_t pack_bf2(float lo, float hi) {
    uint32_t r; asm("cvt.rn.bf16x2.f32 %0, %1, %2;" : "=r"(r) : "f"(hi), "f"(lo)); return r;
}
__device__ __forceinline__ void split2(float d0, float d1, uint32_t& h, uint32_t& l) {
    h = pack_bf2(d0, d1);
    float h0 = __uint_as_float(h << 16);
    float h1 = __uint_as_float(h & 0xFFFF0000u);
    l = pack_bf2(d0 - h0, d1 - h1);
}
// D' = 2^(c2t + 2S p1.pt) - 2^(c2n + 2S p1.pn)   (c1 factored out)
__device__ __forceinline__ float dpair(float4 P, float4 pt, float4 pn) {
    float et = ex2f(fmaf(P.x, pt.x, fmaf(P.y, pt.y, fmaf(P.z, pt.z, pt.w))));
    float en = ex2f(fmaf(P.x, pn.x, fmaf(P.y, pn.y, fmaf(P.z, pn.z, pn.w))));
    return et - en;
}
__device__ __forceinline__ void mma_bf16(float* c, const uint32_t* a, const uint32_t* b) {
    asm volatile(
        "mma.sync.aligned.m16n8k16.row.col.f32.bf16.bf16.f32 "
        "{%0,%1,%2,%3}, {%4,%5,%6,%7}, {%8,%9}, {%0,%1,%2,%3};"
        : "+f"(c[0]), "+f"(c[1]), "+f"(c[2]), "+f"(c[3])
        : "r"(a[0]), "r"(a[1]), "r"(a[2]), "r"(a[3]), "r"(b[0]), "r"(b[1]));
}

// ---------------- kernels ----------------
__global__ void prep_kernel(const float* __restrict__ f1,
                            const float* __restrict__ f2,
                            const float* __restrict__ d1,
                            const float* __restrict__ d2,
                            const float* __restrict__ pose,
                            const float* __restrict__ yz1) {
    int gid = blockIdx.x * blockDim.x + threadIdx.x;   // BB*NN threads
    int b = gid / NN, i = gid % NN;

    float dd1 = d1[gid], dd2 = d2[gid];
    float m1 = dd1 > 0.f ? 1.f : 0.f;
    float m2 = dd2 > 0.f ? 1.f : 0.f;

    float gx = yz1[i], gy = yz1[NN + i], gz = yz1[2 * NN + i];
    float x1 = gx * dd1, y1 = gy * dd1, z1 = gz * dd1;
    float x2 = gx * dd2, y2 = gy * dd2, z2 = gz * dd2;

    const float* Pm = pose + b * 16;
    float xt = Pm[0]*x2 + Pm[1]*y2 + Pm[2] *z2 + Pm[3];
    float yt = Pm[4]*x2 + Pm[5]*y2 + Pm[6] *z2 + Pm[7];
    float zt = Pm[8]*x2 + Pm[9]*y2 + Pm[10]*z2 + Pm[11];

    float q1 = x1*x1 + y1*y1 + z1*z1;
    float e1 = ex2f(-S1 * q1);                       // 2^{c1}
    g_p1s[gid] = make_float4(S2*x1, S2*y1, S2*z1, e1);
    g_p2t[gid] = make_float4(xt, yt, zt, -S1*(xt*xt + yt*yt + zt*zt));
    g_p2n[gid] = make_float4(x2, y2, z2, -S1*(x2*x2 + y2*y2 + z2*z2));

    float a1[CC], a2[CC];
    float s1 = 0.f, s2 = 0.f;
#pragma unroll
    for (int c = 0; c < CC; c++) {
        float v = f1[(b * CC + c) * NN + i]; a1[c] = v; s1 += v * v;
        float w = f2[(b * CC + c) * NN + i]; a2[c] = w; s2 += w * w;
    }
    float n1 = sqrtf(s1), n2 = sqrtf(s2);
    float r1 = m1 / (n1 + 1e-8f), r2 = m2 / (n2 + 1e-8f);
#pragma unroll
    for (int c = 0; c < CC; c++) {
        g_f1e[gid * CC + c] = a1[c] * r1 * e1;       // fold 2^{c1} into f1
        float w = a2[c] * r2;
        unsigned short hb = bf16_bits(w);
        float hv = bf16_val(hb);
        g_f2h[(b * CC + c) * NN + i] = hb;
        g_f2l[(b * CC + c) * NN + i] = bf16_bits(w - hv);
    }

    float vm1 = m1, vm2 = m2, vf = 100.f * (n1 * m1 + n2 * m2);
#pragma unroll
    for (int o = 16; o > 0; o >>= 1) {
        vm1 += __shfl_down_sync(0xffffffffu, vm1, o);
        vm2 += __shfl_down_sync(0xffffffffu, vm2, o);
        vf  += __shfl_down_sync(0xffffffffu, vf,  o);
    }
    if ((threadIdx.x & 31) == 0) {
        atomicAdd(&g_sm1[b], (double)vm1);
        atomicAdd(&g_sm2[b], (double)vm2);
        atomicAdd(&g_fns,    (double)vf);
    }
}

__global__ __launch_bounds__(BT, 6) void pair_kernel(float* __restrict__ out, int out_size) {
    const int b    = blockIdx.z;
    const int base = b * NN;
    const int ibase = blockIdx.y * IT;
    const int warp = threadIdx.x >> 5, lane = threadIdx.x & 31;
    const int r = lane >> 2, cq = lane & 3;          // groupID, tid-in-group

    __shared__ float4 spt[JCH], spn[JCH];
    __shared__ unsigned short sfh[CC][JPAD], sfl[CC][JPAD];
    __shared__ float wred[BT / 32];
    __shared__ int is_last;

    // this lane's 4 p1 rows (rows r, r+8 of each 16-row A fragment)
    float4 P[4];
#pragma unroll
    for (int t = 0; t < 4; t++)
        P[t] = g_p1s[base + ibase + warp * MW + 8 * t + r];

    float acc[2][2][4];                              // [rowfrag][nhalf][4]
#pragma unroll
    for (int a = 0; a < 2; a++)
#pragma unroll
        for (int n = 0; n < 2; n++)
#pragma unroll
            for (int k = 0; k < 4; k++) acc[a][n][k] = 0.f;

    for (int ch = 0; ch < JBLK / JCH; ch++) {
        const int j0 = blockIdx.x * JBLK + ch * JCH;
        __syncthreads();
        for (int idx = threadIdx.x; idx < JCH; idx += BT) {
            spt[idx] = g_p2t[base + j0 + idx];
            spn[idx] = g_p2n[base + j0 + idx];
        }
        for (int idx = threadIdx.x; idx < CC * (JCH / 2); idx += BT) {
            int c = idx >> 6, jj = idx & 63;
            ((uint32_t*)&sfh[c][0])[jj] = ((const uint32_t*)(g_f2h + (b * CC + c) * NN + j0))[jj];
            ((uint32_t*)&sfl[c][0])[jj] = ((const uint32_t*)(g_f2l + (b * CC + c) * NN + j0))[jj];
        }
        __syncthreads();

#pragma unroll 1
        for (int ks = 0; ks < JCH / 16; ks++) {
            const int kb = ks * 16 + 2 * cq;
            float4 pt0 = spt[kb], pt1 = spt[kb + 1], pt8 = spt[kb + 8], pt9 = spt[kb + 9];
            float4 pn0 = spn[kb], pn1 = spn[kb + 1], pn8 = spn[kb + 8], pn9 = spn[kb + 9];

            uint32_t bh[2][2], bl[2][2];
#pragma unroll
            for (int nh = 0; nh < 2; nh++) {
                bh[nh][0] = *(const uint32_t*)&sfh[nh * 8 + r][kb];
                bh[nh][1] = *(const uint32_t*)&sfh[nh * 8 + r][kb + 8];
                bl[nh][0] = *(const uint32_t*)&sfl[nh * 8 + r][kb];
                bl[nh][1] = *(const uint32_t*)&sfl[nh * 8 + r][kb + 8];
            }
#pragma unroll
            for (int rf = 0; rf < 2; rf++) {
                float4 A0 = P[2 * rf], A1 = P[2 * rf + 1];
                float d00 = dpair(A0, pt0, pn0), d01 = dpair(A0, pt1, pn1);
                float d10 = dpair(A1, pt0, pn0), d11 = dpair(A1, pt1, pn1);
                float d08 = dpair(A0, pt8, pn8), d09 = dpair(A0, pt9, pn9);
                float d18 = dpair(A1, pt8, pn8), d19 = dpair(A1, pt9, pn9);
                uint32_t ah[4], al[4];
                split2(d00, d01, ah[0], al[0]);
                split2(d10, d11, ah[1], al[1]);
                split2(d08, d09, ah[2], al[2]);
                split2(d18, d19, ah[3], al[3]);
#pragma unroll
                for (int nh = 0; nh < 2; nh++) {
                    mma_bf16(acc[rf][nh], ah, bh[nh]);
                    mma_bf16(acc[rf][nh], ah, bl[nh]);
                    mma_bf16(acc[rf][nh], al, bh[nh]);
                }
            }
        }
    }

    // epilogue: contract C with f1e (e_c1 already folded in)
    float tot = 0.f;
#pragma unroll
    for (int rf = 0; rf < 2; rf++) {
#pragma unroll
        for (int nh = 0; nh < 2; nh++) {
            const float* F0 = g_f1e + (base + ibase + warp * MW + rf * 16 + r) * CC + nh * 8 + 2 * cq;
            const float* F1 = F0 + 8 * CC;
            tot += acc[rf][nh][0] * F0[0] + acc[rf][nh][1] * F0[1]
                 + acc[rf][nh][2] * F1[0] + acc[rf][nh][3] * F1[1];
        }
    }
#pragma unroll
    for (int o = 16; o > 0; o >>= 1) tot += __shfl_down_sync(0xffffffffu, tot, o);
    if (lane == 0) wred[warp] = tot;
    __syncthreads();
    if (threadIdx.x == 0) {
        float s = wred[0] + wred[1] + wred[2] + wred[3];
        atomicAdd(&g_acc[b], (double)s);
        __threadfence();
        unsigned int t = atomicAdd(&g_cnt, 1u);
        is_last = (t == NBLK - 1) ? 1 : 0;
    }
    __syncthreads();

    // last block: finalize + self-reset (graph-replay deterministic)
    if (is_last) {
        if (threadIdx.x == 0) {
            __threadfence();
            double total = 0.0;
            for (int bb = 0; bb < BB; bb++)
                total += -g_acc[bb] / (g_sm1[bb] * g_sm2[bb]);
            if (out_size > 0) out[0] = (float)total;
            if (out_size > 1) out[1] = (float)total;
            if (out_size > 2) out[2] = (float)g_fns;
            for (int bb = 0; bb < BB; bb++) { g_acc[bb] = 0.0; g_sm1[bb] = 0.0; g_sm2[bb] = 0.0; }
            g_fns = 0.0;
            g_cnt = 0u;
        }
        for (int idx = threadIdx.x + 3; idx < out_size; idx += BT) out[idx] = 0.f;
    }
}

extern "C" void kernel_launch(void* const* d_in, const int* in_sizes, int n_in,
                              void* d_out, int out_size) {
    const float* f1   = (const float*)d_in[0];
    const float* f2   = (const float*)d_in[1];
    const float* d1   = (const float*)d_in[2];
    const float* d2   = (const float*)d_in[3];
    const float* pose = (const float*)d_in[4];
    const float* yz1  = (const float*)d_in[7];
    float* out = (float*)d_out;

    prep_kernel<<<(BB * NN) / 256, 256>>>(f1, f2, d1, d2, pose, yz1);
    pair_kernel<<<dim3(JSPLIT, NN / IT, BB), BT>>>(out, out_size);
}

// round 5
// speedup vs baseline: 2.4800x; 1.7052x over previous
#include <cuda_runtime.h>
#include <cuda_fp16.h>
#include <cstdint>

#define BB 2
#define CC 16
#define NN 6912          // 72*96
#define BT 128           // threads per block (4 warps)
#define MW 32            // i rows per warp
#define IT 128           // i rows per block
#define JCH 128          // j chunk in smem
#define JPAD 136         // padded j stride for f2 tile
#define BSTR 24          // padded half-stride for arg-B tables (48B rows, conflict-free)
#define JSPLIT 18
#define JBLK (NN / JSPLIT)                 // 384 j per block
#define NBLK (JSPLIT * (NN / IT) * BB)     // 1944 pair blocks

#define S1 14.426950408889634f   // 10*log2(e)
#define S2 28.853900817779268f   // 20*log2(e)

// ---------------- scratch ----------------
__device__ __half g_a1h[BB * NN * 16];   // A' table: [Ah(5), Al(5), Ah(5), 0] per i
__device__ __half g_bth[BB * NN * 16];   // B' table (pose-transformed): [Bh,Bh,Bl,0] per j
__device__ __half g_bnh[BB * NN * 16];   // B' table (noisy)
__device__ float  g_f1e[BB * NN * CC];   // f1 normalized*mask, [b][i][c]
__device__ __half g_f2h[BB * CC * NN];   // f2 normalized*mask fp16, [b][c][j]
__device__ double g_acc[BB];
__device__ double g_sm1[BB], g_sm2[BB];
__device__ double g_fns;
__device__ unsigned int g_cnt;           // completion counter (self-resetting)

// ---------------- helpers ----------------
__device__ __forceinline__ float ex2f(float x) {
    float r; asm("ex2.approx.ftz.f32 %0, %1;" : "=f"(r) : "f"(x)); return r;
}
// D pair: 2^argT - 2^argN in fp16x2, packed along j
__device__ __forceinline__ uint32_t dexp(float t0, float t1, float n0, float n1) {
    __half2 ht = __floats2half2_rn(t0, t1);
    __half2 hn = __floats2half2_rn(n0, n1);
    uint32_t ut = *(uint32_t*)&ht, un = *(uint32_t*)&hn, rt, rn;
    asm("ex2.approx.f16x2 %0, %1;" : "=r"(rt) : "r"(ut));
    asm("ex2.approx.f16x2 %0, %1;" : "=r"(rn) : "r"(un));
    __half2 d = __hsub2(*(__half2*)&rt, *(__half2*)&rn);
    return *(uint32_t*)&d;
}
__device__ __forceinline__ void mma_f16(float* c, const uint32_t* a, const uint32_t* b) {
    asm volatile(
        "mma.sync.aligned.m16n8k16.row.col.f32.f16.f16.f32 "
        "{%0,%1,%2,%3}, {%4,%5,%6,%7}, {%8,%9}, {%0,%1,%2,%3};"
        : "+f"(c[0]), "+f"(c[1]), "+f"(c[2]), "+f"(c[3])
        : "r"(a[0]), "r"(a[1]), "r"(a[2]), "r"(a[3]), "r"(b[0]), "r"(b[1]));
}
// build [h(5), l(5), h(5), 0]  (A-side k layout)
__device__ __forceinline__ void split5_A(const float* v, __half* o) {
#pragma unroll
    for (int k = 0; k < 5; k++) {
        __half h = __float2half_rn(v[k]);
        o[k] = h; o[10 + k] = h;
        o[5 + k] = __float2half_rn(v[k] - __half2float(h));
    }
    o[15] = __float2half_rn(0.f);
}
// build [h(5), h(5), l(5), 0]  (B-side k layout)
__device__ __forceinline__ void split5_B(const float* v, __half* o) {
#pragma unroll
    for (int k = 0; k < 5; k++) {
        __half h = __float2half_rn(v[k]);
        o[k] = h; o[5 + k] = h;
        o[10 + k] = __float2half_rn(v[k] - __half2float(h));
    }
    o[15] = __float2half_rn(0.f);
}

// ---------------- kernels ----------------
__global__ void prep_kernel(const float* __restrict__ f1,
                            const float* __restrict__ f2,
                            const float* __restrict__ d1,
                            const float* __restrict__ d2,
                            const float* __restrict__ pose,
                            const float* __restrict__ yz1) {
    int gid = blockIdx.x * blockDim.x + threadIdx.x;   // BB*NN threads
    int b = gid / NN, i = gid % NN;

    float dd1 = d1[gid], dd2 = d2[gid];
    float m1 = dd1 > 0.f ? 1.f : 0.f;
    float m2 = dd2 > 0.f ? 1.f : 0.f;

    float gx = yz1[i], gy = yz1[NN + i], gz = yz1[2 * NN + i];
    float x1 = gx * dd1, y1 = gy * dd1, z1 = gz * dd1;
    float x2 = gx * dd2, y2 = gy * dd2, z2 = gz * dd2;

    const float* Pm = pose + b * 16;
    float xt = Pm[0]*x2 + Pm[1]*y2 + Pm[2] *z2 + Pm[3];
    float yt = Pm[4]*x2 + Pm[5]*y2 + Pm[6] *z2 + Pm[7];
    float zt = Pm[8]*x2 + Pm[9]*y2 + Pm[10]*z2 + Pm[11];

    float c1 = -S1 * (x1*x1 + y1*y1 + z1*z1);

    // A' table for i
    {
        float a5[5] = {S2 * x1, S2 * y1, S2 * z1, c1, 1.f};
        __half o[16];
        split5_A(a5, o);
        *(uint4*)&g_a1h[gid * 16]     = *(uint4*)&o[0];
        *(uint4*)&g_a1h[gid * 16 + 8] = *(uint4*)&o[8];
    }
    // B' tables for j
    {
        float bt5[5] = {xt, yt, zt, 1.f, -S1 * (xt*xt + yt*yt + zt*zt)};
        float bn5[5] = {x2, y2, z2, 1.f, -S1 * (x2*x2 + y2*y2 + z2*z2)};
        __half o[16];
        split5_B(bt5, o);
        *(uint4*)&g_bth[gid * 16]     = *(uint4*)&o[0];
        *(uint4*)&g_bth[gid * 16 + 8] = *(uint4*)&o[8];
        split5_B(bn5, o);
        *(uint4*)&g_bnh[gid * 16]     = *(uint4*)&o[0];
        *(uint4*)&g_bnh[gid * 16 + 8] = *(uint4*)&o[8];
    }

    float a1[CC], a2[CC];
    float s1 = 0.f, s2 = 0.f;
#pragma unroll
    for (int c = 0; c < CC; c++) {
        float v = f1[(b * CC + c) * NN + i]; a1[c] = v; s1 += v * v;
        float w = f2[(b * CC + c) * NN + i]; a2[c] = w; s2 += w * w;
    }
    float n1 = sqrtf(s1), n2 = sqrtf(s2);
    float r1 = m1 / (n1 + 1e-8f), r2 = m2 / (n2 + 1e-8f);
#pragma unroll
    for (int c = 0; c < CC; c++) {
        g_f1e[gid * CC + c] = a1[c] * r1;
        g_f2h[(b * CC + c) * NN + i] = __float2half_rn(a2[c] * r2);
    }

    float vm1 = m1, vm2 = m2, vf = 100.f * (n1 * m1 + n2 * m2);
#pragma unroll
    for (int o = 16; o > 0; o >>= 1) {
        vm1 += __shfl_down_sync(0xffffffffu, vm1, o);
        vm2 += __shfl_down_sync(0xffffffffu, vm2, o);
        vf  += __shfl_down_sync(0xffffffffu, vf,  o);
    }
    if ((threadIdx.x & 31) == 0) {
        atomicAdd(&g_sm1[b], (double)vm1);
        atomicAdd(&g_sm2[b], (double)vm2);
        atomicAdd(&g_fns,    (double)vf);
    }
}

__global__ __launch_bounds__(BT, 6) void pair_kernel(float* __restrict__ out, int out_size) {
    const int b    = blockIdx.z;
    const int base = b * NN;
    const int ibase = blockIdx.y * IT;
    const int warp = threadIdx.x >> 5, lane = threadIdx.x & 31;
    const int r = lane >> 2, cq = lane & 3;

    __shared__ __half sbT[JCH][BSTR];        // arg-B' (pose) tiles
    __shared__ __half sbN[JCH][BSTR];        // arg-B' (noisy)
    __shared__ __half sf [CC][JPAD];         // f2 fp16
    __shared__ float wred[BT / 32];
    __shared__ int is_last;

    // persistent A fragments for the two 16-row i halves
    uint32_t aA[2][4];
#pragma unroll
    for (int rf = 0; rf < 2; rf++) {
        const __half* A0 = g_a1h + (size_t)(base + ibase + warp * MW + rf * 16 + r) * 16;
        const __half* A8 = A0 + 8 * 16;
        aA[rf][0] = *(const uint32_t*)(A0 + 2 * cq);
        aA[rf][1] = *(const uint32_t*)(A8 + 2 * cq);
        aA[rf][2] = *(const uint32_t*)(A0 + 2 * cq + 8);
        aA[rf][3] = *(const uint32_t*)(A8 + 2 * cq + 8);
    }

    float acc[2][2][4];                      // [rf][channel-half][4]
#pragma unroll
    for (int a = 0; a < 2; a++)
#pragma unroll
        for (int n = 0; n < 2; n++)
#pragma unroll
            for (int k = 0; k < 4; k++) acc[a][n][k] = 0.f;

    for (int ch = 0; ch < JBLK / JCH; ch++) {
        const int j0 = blockIdx.x * JBLK + ch * JCH;
        __syncthreads();
        {   // arg-B tables: 32B per j -> padded 48B rows
            int j = threadIdx.x;  // JCH == BT
            const uint4* srcT = (const uint4*)(g_bth + (size_t)(base + j0 + j) * 16);
            const uint4* srcN = (const uint4*)(g_bnh + (size_t)(base + j0 + j) * 16);
            *(uint4*)&sbT[j][0] = srcT[0];
            *(uint4*)&sbT[j][8] = srcT[1];
            *(uint4*)&sbN[j][0] = srcN[0];
            *(uint4*)&sbN[j][8] = srcN[1];
        }
        for (int idx = threadIdx.x; idx < CC * 16; idx += BT) {
            int c = idx >> 4, seg = idx & 15;
            *(uint4*)&sf[c][seg * 8] =
                *(const uint4*)(g_f2h + (size_t)(b * CC + c) * NN + j0 + seg * 8);
        }
        __syncthreads();

#pragma unroll 2
        for (int ks = 0; ks < JCH / 16; ks++) {
            const int jb = ks * 16;
            uint32_t bT[2][2], bN[2][2];
#pragma unroll
            for (int h = 0; h < 2; h++) {
                const __half* pT = &sbT[jb + h * 8 + r][0];
                const __half* pN = &sbN[jb + h * 8 + r][0];
                bT[h][0] = *(const uint32_t*)(pT + 2 * cq);
                bT[h][1] = *(const uint32_t*)(pT + 2 * cq + 8);
                bN[h][0] = *(const uint32_t*)(pN + 2 * cq);
                bN[h][1] = *(const uint32_t*)(pN + 2 * cq + 8);
            }
            uint32_t bg[2][2];
#pragma unroll
            for (int nc = 0; nc < 2; nc++) {
                bg[nc][0] = *(const uint32_t*)&sf[nc * 8 + r][jb + 2 * cq];
                bg[nc][1] = *(const uint32_t*)&sf[nc * 8 + r][jb + 2 * cq + 8];
            }
#pragma unroll
            for (int rf = 0; rf < 2; rf++) {
                float cT[2][4] = {{0.f,0.f,0.f,0.f},{0.f,0.f,0.f,0.f}};
                float cN[2][4] = {{0.f,0.f,0.f,0.f},{0.f,0.f,0.f,0.f}};
                mma_f16(cT[0], aA[rf], bT[0]);
                mma_f16(cT[1], aA[rf], bT[1]);
                mma_f16(cN[0], aA[rf], bN[0]);
                mma_f16(cN[1], aA[rf], bN[1]);
                uint32_t d[4];
                d[0] = dexp(cT[0][0], cT[0][1], cN[0][0], cN[0][1]);
                d[1] = dexp(cT[0][2], cT[0][3], cN[0][2], cN[0][3]);
                d[2] = dexp(cT[1][0], cT[1][1], cN[1][0], cN[1][1]);
                d[3] = dexp(cT[1][2], cT[1][3], cN[1][2], cN[1][3]);
                mma_f16(acc[rf][0], d, bg[0]);
                mma_f16(acc[rf][1], d, bg[1]);
            }
        }
    }

    // epilogue: contract C with f1 (normalized, masked)
    float tot = 0.f;
#pragma unroll
    for (int rf = 0; rf < 2; rf++) {
#pragma unroll
        for (int nc = 0; nc < 2; nc++) {
            const float* F0 = g_f1e + (size_t)(base + ibase + warp * MW + rf * 16 + r) * CC + nc * 8 + 2 * cq;
            const float* F1 = F0 + 8 * CC;
            tot += acc[rf][nc][0] * F0[0] + acc[rf][nc][1] * F0[1]
                 + acc[rf][nc][2] * F1[0] + acc[rf][nc][3] * F1[1];
        }
    }
#pragma unroll
    for (int o = 16; o > 0; o >>= 1) tot += __shfl_down_sync(0xffffffffu, tot, o);
    if (lane == 0) wred[warp] = tot;
    __syncthreads();
    if (threadIdx.x == 0) {
        float s = wred[0] + wred[1] + wred[2] + wred[3];
        atomicAdd(&g_acc[b], (double)s);
        __threadfence();
        unsigned int t = atomicAdd(&g_cnt, 1u);
        is_last = (t == NBLK - 1) ? 1 : 0;
    }
    __syncthreads();

    if (is_last) {
        if (threadIdx.x == 0) {
            __threadfence();
            double total = 0.0;
            for (int bb = 0; bb < BB; bb++)
                total += -g_acc[bb] / (g_sm1[bb] * g_sm2[bb]);
            if (out_size > 0) out[0] = (float)total;
            if (out_size > 1) out[1] = (float)total;
            if (out_size > 2) out[2] = (float)g_fns;
            for (int bb = 0; bb < BB; bb++) { g_acc[bb] = 0.0; g_sm1[bb] = 0.0; g_sm2[bb] = 0.0; }
            g_fns = 0.0;
            g_cnt = 0u;
        }
        for (int idx = threadIdx.x + 3; idx < out_size; idx += BT) out[idx] = 0.f;
    }
}

extern "C" void kernel_launch(void* const* d_in, const int* in_sizes, int n_in,
                              void* d_out, int out_size) {
    const float* f1   = (const float*)d_in[0];
    const float* f2   = (const float*)d_in[1];
    const float* d1   = (const float*)d_in[2];
    const float* d2   = (const float*)d_in[3];
    const float* pose = (const float*)d_in[4];
    const float* yz1  = (const float*)d_in[7];
    float* out = (float*)d_out;

    prep_kernel<<<(BB * NN) / 256, 256>>>(f1, f2, d1, d2, pose, yz1);
    pair_kernel<<<dim3(JSPLIT, NN / IT, BB), BT>>>(out, out_size);
}

// round 8
// speedup vs baseline: 2.7900x; 1.1250x over previous
#include <cuda_runtime.h>
#include <cuda_fp16.h>
#include <cstdint>

#define BB 2
#define CC 16
#define NN 6912          // 72*96
#define BT 128           // threads per block (4 warps)
#define MW 32            // i rows per warp
#define IT 128           // i rows per block
#define JCH 128          // j chunk in smem
#define JPAD 136         // padded j stride for f2 tile (halfwords)
#define BSTR 24          // padded stride for arg-B tables (halfwords, 48B rows)
#define JSPLIT 18
#define JBLK (NN / JSPLIT)                 // 384 j per block
#define NBLK (JSPLIT * (NN / IT) * BB)     // 1944 pair blocks

#define S1 14.426950408889634f   // 10*log2(e)
#define S2 28.853900817779268f   // 20*log2(e)

// ---------------- scratch ----------------
__device__ __half g_a1h[BB * NN * 16];   // A' table: [Ah(5), Al(5), Ah(5), 0] per i
__device__ __half g_bth[BB * NN * 16];   // B' table (pose-transformed): [Bh,Bh,Bl,0] per j
__device__ __half g_bnh[BB * NN * 16];   // B' table (noisy)
__device__ float  g_f1e[BB * NN * CC];   // f1 normalized*mask, [b][i][c]
__device__ __half g_f2h[BB * CC * NN];   // f2 normalized*mask fp16, [b][c][j]
__device__ double g_acc[BB];
__device__ double g_sm1[BB], g_sm2[BB];
__device__ double g_fns;
__device__ unsigned int g_cnt;           // completion counter (self-resetting)

// ---------------- helpers ----------------
// D pair: 2^t - 2^n on packed f16x2
__device__ __forceinline__ uint32_t dexp2(uint32_t t, uint32_t n) {
    uint32_t rt, rn;
    asm("ex2.approx.f16x2 %0, %1;" : "=r"(rt) : "r"(t));
    asm("ex2.approx.f16x2 %0, %1;" : "=r"(rn) : "r"(n));
    __half2 d = __hsub2(*(__half2*)&rt, *(__half2*)&rn);
    return *(uint32_t*)&d;
}
// f32-accum gram MMA
__device__ __forceinline__ void mma_f16(float* c, const uint32_t* a, const uint32_t* b) {
    asm volatile(
        "mma.sync.aligned.m16n8k16.row.col.f32.f16.f16.f32 "
        "{%0,%1,%2,%3}, {%4,%5,%6,%7}, {%8,%9}, {%0,%1,%2,%3};"
        : "+f"(c[0]), "+f"(c[1]), "+f"(c[2]), "+f"(c[3])
        : "r"(a[0]), "r"(a[1]), "r"(a[2]), "r"(a[3]), "r"(b[0]), "r"(b[1]));
}
// f16-accum arg MMA, C = 0 (distinct zero registers; in/out via "+r")
__device__ __forceinline__ void mma_f16d(uint32_t* d, const uint32_t* a, const uint32_t* b) {
    d[0] = 0u; d[1] = 0u;
    asm volatile(
        "mma.sync.aligned.m16n8k16.row.col.f16.f16.f16.f16 "
        "{%0,%1}, {%2,%3,%4,%5}, {%6,%7}, {%0,%1};"
        : "+r"(d[0]), "+r"(d[1])
        : "r"(a[0]), "r"(a[1]), "r"(a[2]), "r"(a[3]), "r"(b[0]), "r"(b[1]));
}
__device__ __forceinline__ void ldsm4(uint32_t* r, uint32_t addr) {
    asm volatile("ldmatrix.sync.aligned.m8n8.x4.shared.b16 {%0,%1,%2,%3}, [%4];"
        : "=r"(r[0]), "=r"(r[1]), "=r"(r[2]), "=r"(r[3]) : "r"(addr));
}
__device__ __forceinline__ uint32_t smem_u32(const void* p) {
    return (uint32_t)__cvta_generic_to_shared(p);
}
// build [h(5), l(5), h(5), 0]  (A-side k layout)
__device__ __forceinline__ void split5_A(const float* v, __half* o) {
#pragma unroll
    for (int k = 0; k < 5; k++) {
        __half h = __float2half_rn(v[k]);
        o[k] = h; o[10 + k] = h;
        o[5 + k] = __float2half_rn(v[k] - __half2float(h));
    }
    o[15] = __float2half_rn(0.f);
}
// build [h(5), h(5), l(5), 0]  (B-side k layout)
__device__ __forceinline__ void split5_B(const float* v, __half* o) {
#pragma unroll
    for (int k = 0; k < 5; k++) {
        __half h = __float2half_rn(v[k]);
        o[k] = h; o[5 + k] = h;
        o[10 + k] = __float2half_rn(v[k] - __half2float(h));
    }
    o[15] = __float2half_rn(0.f);
}

// ---------------- kernels ----------------
__global__ void prep_kernel(const float* __restrict__ f1,
                            const float* __restrict__ f2,
                            const float* __restrict__ d1,
                            const float* __restrict__ d2,
                            const float* __restrict__ pose,
                            const float* __restrict__ yz1) {
    int gid = blockIdx.x * blockDim.x + threadIdx.x;   // BB*NN threads
    int b = gid / NN, i = gid % NN;

    float dd1 = d1[gid], dd2 = d2[gid];
    float m1 = dd1 > 0.f ? 1.f : 0.f;
    float m2 = dd2 > 0.f ? 1.f : 0.f;

    float gx = yz1[i], gy = yz1[NN + i], gz = yz1[2 * NN + i];
    float x1 = gx * dd1, y1 = gy * dd1, z1 = gz * dd1;
    float x2 = gx * dd2, y2 = gy * dd2, z2 = gz * dd2;

    const float* Pm = pose + b * 16;
    float xt = Pm[0]*x2 + Pm[1]*y2 + Pm[2] *z2 + Pm[3];
    float yt = Pm[4]*x2 + Pm[5]*y2 + Pm[6] *z2 + Pm[7];
    float zt = Pm[8]*x2 + Pm[9]*y2 + Pm[10]*z2 + Pm[11];

    float c1 = -S1 * (x1*x1 + y1*y1 + z1*z1);

    {
        float a5[5] = {S2 * x1, S2 * y1, S2 * z1, c1, 1.f};
        __half o[16];
        split5_A(a5, o);
        *(uint4*)&g_a1h[gid * 16]     = *(uint4*)&o[0];
        *(uint4*)&g_a1h[gid * 16 + 8] = *(uint4*)&o[8];
    }
    {
        float bt5[5] = {xt, yt, zt, 1.f, -S1 * (xt*xt + yt*yt + zt*zt)};
        float bn5[5] = {x2, y2, z2, 1.f, -S1 * (x2*x2 + y2*y2 + z2*z2)};
        __half o[16];
        split5_B(bt5, o);
        *(uint4*)&g_bth[gid * 16]     = *(uint4*)&o[0];
        *(uint4*)&g_bth[gid * 16 + 8] = *(uint4*)&o[8];
        split5_B(bn5, o);
        *(uint4*)&g_bnh[gid * 16]     = *(uint4*)&o[0];
        *(uint4*)&g_bnh[gid * 16 + 8] = *(uint4*)&o[8];
    }

    float a1[CC], a2[CC];
    float s1 = 0.f, s2 = 0.f;
#pragma unroll
    for (int c = 0; c < CC; c++) {
        float v = f1[(b * CC + c) * NN + i]; a1[c] = v; s1 += v * v;
        float w = f2[(b * CC + c) * NN + i]; a2[c] = w; s2 += w * w;
    }
    float n1 = sqrtf(s1), n2 = sqrtf(s2);
    float r1 = m1 / (n1 + 1e-8f), r2 = m2 / (n2 + 1e-8f);
#pragma unroll
    for (int c = 0; c < CC; c++) {
        g_f1e[gid * CC + c] = a1[c] * r1;
        g_f2h[(b * CC + c) * NN + i] = __float2half_rn(a2[c] * r2);
    }

    float vm1 = m1, vm2 = m2, vf = 100.f * (n1 * m1 + n2 * m2);
#pragma unroll
    for (int o = 16; o > 0; o >>= 1) {
        vm1 += __shfl_down_sync(0xffffffffu, vm1, o);
        vm2 += __shfl_down_sync(0xffffffffu, vm2, o);
        vf  += __shfl_down_sync(0xffffffffu, vf,  o);
    }
    if ((threadIdx.x & 31) == 0) {
        atomicAdd(&g_sm1[b], (double)vm1);
        atomicAdd(&g_sm2[b], (double)vm2);
        atomicAdd(&g_fns,    (double)vf);
    }
}

__global__ __launch_bounds__(BT, 8) void pair_kernel(float* __restrict__ out, int out_size) {
    const int b    = blockIdx.z;
    const int base = b * NN;
    const int ibase = blockIdx.y * IT;
    const int warp = threadIdx.x >> 5, lane = threadIdx.x & 31;
    const int r = lane >> 2, cq = lane & 3;

    __shared__ __half sbT[JCH][BSTR];        // arg-B' (pose) tile
    __shared__ __half sbN[JCH][BSTR];        // arg-B' (noisy)
    __shared__ __half sf [CC][JPAD];         // f2 fp16
    __shared__ float wred[BT / 32];
    __shared__ int is_last;

    // persistent A fragments for the two 16-row i halves
    uint32_t aA[2][4];
#pragma unroll
    for (int rf = 0; rf < 2; rf++) {
        const __half* A0 = g_a1h + (size_t)(base + ibase + warp * MW + rf * 16 + r) * 16;
        const __half* A8 = A0 + 8 * 16;
        aA[rf][0] = *(const uint32_t*)(A0 + 2 * cq);
        aA[rf][1] = *(const uint32_t*)(A8 + 2 * cq);
        aA[rf][2] = *(const uint32_t*)(A0 + 2 * cq + 8);
        aA[rf][3] = *(const uint32_t*)(A8 + 2 * cq + 8);
    }

    // ldmatrix per-lane base addresses: matrix m = lane>>3, row rr = lane&7
    const int lm = lane >> 3, rr = lane & 7;
    const uint32_t adrT0 = smem_u32(&sbT[0][0]) + (((lm >> 1) * 8 + rr) * BSTR + (lm & 1) * 8) * 2;
    const uint32_t adrN0 = smem_u32(&sbN[0][0]) + (((lm >> 1) * 8 + rr) * BSTR + (lm & 1) * 8) * 2;
    const uint32_t adrG0 = smem_u32(&sf[0][0])  + (((lm >> 1) * 8 + rr) * JPAD + (lm & 1) * 8) * 2;

    float acc[2][2][4];
#pragma unroll
    for (int a = 0; a < 2; a++)
#pragma unroll
        for (int n = 0; n < 2; n++)
#pragma unroll
            for (int k = 0; k < 4; k++) acc[a][n][k] = 0.f;

    for (int ch = 0; ch < JBLK / JCH; ch++) {
        const int j0 = blockIdx.x * JBLK + ch * JCH;
        __syncthreads();
        {   // arg-B tables: 32B per j -> padded 48B rows
            int j = threadIdx.x;  // JCH == BT
            const uint4* srcT = (const uint4*)(g_bth + (size_t)(base + j0 + j) * 16);
            const uint4* srcN = (const uint4*)(g_bnh + (size_t)(base + j0 + j) * 16);
            *(uint4*)&sbT[j][0] = srcT[0];
            *(uint4*)&sbT[j][8] = srcT[1];
            *(uint4*)&sbN[j][0] = srcN[0];
            *(uint4*)&sbN[j][8] = srcN[1];
        }
        for (int idx = threadIdx.x; idx < CC * 16; idx += BT) {
            int c = idx >> 4, seg = idx & 15;
            *(uint4*)&sf[c][seg * 8] =
                *(const uint4*)(g_f2h + (size_t)(b * CC + c) * NN + j0 + seg * 8);
        }
        __syncthreads();

        uint32_t aT = adrT0, aN = adrN0, aG = adrG0;
#pragma unroll 4
        for (int ks = 0; ks < JCH / 16; ks++) {
            uint32_t bT[4], bN[4], bg[4];
            ldsm4(bT, aT);  aT += 16 * BSTR * 2;
            ldsm4(bN, aN);  aN += 16 * BSTR * 2;
            ldsm4(bg, aG);  aG += 16 * 2;
#pragma unroll
            for (int rf = 0; rf < 2; rf++) {
                uint32_t dT0[2], dT1[2], dN0[2], dN1[2];
                mma_f16d(dT0, aA[rf], bT + 0);
                mma_f16d(dT1, aA[rf], bT + 2);
                mma_f16d(dN0, aA[rf], bN + 0);
                mma_f16d(dN1, aA[rf], bN + 2);
                uint32_t d[4];
                d[0] = dexp2(dT0[0], dN0[0]);
                d[1] = dexp2(dT0[1], dN0[1]);
                d[2] = dexp2(dT1[0], dN1[0]);
                d[3] = dexp2(dT1[1], dN1[1]);
                mma_f16(acc[rf][0], d, bg + 0);
                mma_f16(acc[rf][1], d, bg + 2);
            }
        }
    }

    // epilogue: contract C with f1 (normalized, masked)
    float tot = 0.f;
#pragma unroll
    for (int rf = 0; rf < 2; rf++) {
#pragma unroll
        for (int nc = 0; nc < 2; nc++) {
            const float* F0 = g_f1e + (size_t)(base + ibase + warp * MW + rf * 16 + r) * CC + nc * 8 + 2 * cq;
            const float* F1 = F0 + 8 * CC;
            tot += acc[rf][nc][0] * F0[0] + acc[rf][nc][1] * F0[1]
                 + acc[rf][nc][2] * F1[0] + acc[rf][nc][3] * F1[1];
        }
    }
#pragma unroll
    for (int o = 16; o > 0; o >>= 1) tot += __shfl_down_sync(0xffffffffu, tot, o);
    if (lane == 0) wred[warp] = tot;
    __syncthreads();
    if (threadIdx.x == 0) {
        float s = wred[0] + wred[1] + wred[2] + wred[3];
        atomicAdd(&g_acc[b], (double)s);
        __threadfence();
        unsigned int t = atomicAdd(&g_cnt, 1u);
        is_last = (t == NBLK - 1) ? 1 : 0;
    }
    __syncthreads();

    if (is_last) {
        if (threadIdx.x == 0) {
            __threadfence();
            double total = 0.0;
            for (int bb = 0; bb < BB; bb++)
                total += -g_acc[bb] / (g_sm1[bb] * g_sm2[bb]);
            if (out_size > 0) out[0] = (float)total;
            if (out_size > 1) out[1] = (float)total;
            if (out_size > 2) out[2] = (float)g_fns;
            for (int bb = 0; bb < BB; bb++) { g_acc[bb] = 0.0; g_sm1[bb] = 0.0; g_sm2[bb] = 0.0; }
            g_fns = 0.0;
            g_cnt = 0u;
        }
        for (int idx = threadIdx.x + 3; idx < out_size; idx += BT) out[idx] = 0.f;
    }
}

extern "C" void kernel_launch(void* const* d_in, const int* in_sizes, int n_in,
                              void* d_out, int out_size) {
    const float* f1   = (const float*)d_in[0];
    const float* f2   = (const float*)d_in[1];
    const float* d1   = (const float*)d_in[2];
    const float* d2   = (const float*)d_in[3];
    const float* pose = (const float*)d_in[4];
    const float* yz1  = (const float*)d_in[7];
    float* out = (float*)d_out;

    prep_kernel<<<(BB * NN) / 256, 256>>>(f1, f2, d1, d2, pose, yz1);
    pair_kernel<<<dim3(JSPLIT, NN / IT, BB), BT>>>(out, out_size);
}